// round 1
// baseline (speedup 1.0000x reference)
#include <cuda_runtime.h>

#define TM 64
#define EPS 1e-5f

// Precomputed derived operands (scratch via __device__ globals — no allocation).
__device__ float g_phoneP[100 * 256];  // phone_table @ W1[64:192]
__device__ float g_midiP[128 * 256];   // midi_table  @ W1[192:256]
__device__ float g_Wfd[64 * 256];      // rows 0..31: f0_w2@W1[0:64]; rows 32..63: dur_w2@W1[256:320]
__device__ float g_bias[256];          // proj_b1 + f0_b2@W1[0:64] + dur_b2@W1[256:320]

__global__ void precompute_kernel(
    const float* __restrict__ f0_w2,       // [32,64]
    const float* __restrict__ f0_b2,       // [64]
    const float* __restrict__ phone_table, // [100,128]
    const float* __restrict__ midi_table,  // [128,64]
    const float* __restrict__ dur_w2,      // [32,64]
    const float* __restrict__ dur_b2,      // [64]
    const float* __restrict__ proj_w1,     // [320,256]
    const float* __restrict__ proj_b1)     // [256]
{
    const int r = blockIdx.x;
    const int c = threadIdx.x;
    if (r < 100) {
        float s = 0.f;
        #pragma unroll 4
        for (int k = 0; k < 128; k++)
            s += phone_table[r * 128 + k] * proj_w1[(64 + k) * 256 + c];
        g_phoneP[r * 256 + c] = s;
    } else if (r < 228) {
        const int m = r - 100;
        float s = 0.f;
        #pragma unroll 4
        for (int k = 0; k < 64; k++)
            s += midi_table[m * 64 + k] * proj_w1[(192 + k) * 256 + c];
        g_midiP[m * 256 + c] = s;
    } else if (r < 260) {
        const int j = r - 228;
        float s = 0.f;
        #pragma unroll 4
        for (int k = 0; k < 64; k++)
            s += f0_w2[j * 64 + k] * proj_w1[k * 256 + c];
        g_Wfd[j * 256 + c] = s;
    } else if (r < 292) {
        const int j = r - 260;
        float s = 0.f;
        #pragma unroll 4
        for (int k = 0; k < 64; k++)
            s += dur_w2[j * 64 + k] * proj_w1[(256 + k) * 256 + c];
        g_Wfd[(32 + j) * 256 + c] = s;
    } else {
        float s = proj_b1[c];
        for (int k = 0; k < 64; k++) {
            s += f0_b2[k] * proj_w1[k * 256 + c];
            s += dur_b2[k] * proj_w1[(256 + k) * 256 + c];
        }
        g_bias[c] = s;
    }
}

// Fused main kernel: per CTA, 64 positions x 256 output channels.
// GEMM1 (K=64) + table adds -> LayerNorm -> ReLU -> GEMM2 (K=256) -> out.
__global__ __launch_bounds__(256, 1)
void cond_enc_main_kernel(
    const float* __restrict__ f0,
    const int*   __restrict__ phone,
    const float* __restrict__ duration,
    const int*   __restrict__ midi,
    const float* __restrict__ f0_w1,   // [32]
    const float* __restrict__ f0_b1,   // [32]
    const float* __restrict__ dur_w1,  // [32]
    const float* __restrict__ dur_b1,  // [32]
    const float* __restrict__ ln_g,    // [256]
    const float* __restrict__ ln_b,    // [256]
    const float* __restrict__ proj_w2, // [256,256]
    const float* __restrict__ proj_b2, // [256]
    float* __restrict__ out,           // [npos,256]
    int npos)
{
    extern __shared__ float sm[];
    float* sA    = sm;               // [64][257] padded: h then relu'd activations
    float* sW    = sA + 64 * 257;    // [64][256]: Wfd, then W2 chunks
    float* sa1   = sW + 64 * 256;    // [64][64]: [f0_h | dur_h]
    float* sbias = sa1 + 64 * 64;    // [256]
    float* sg    = sbias + 256;      // [256]
    float* sb    = sg + 256;         // [256]
    float* sb2   = sb + 256;         // [256]

    const int tid = threadIdx.x;
    const int tx = tid & 31;         // col group: cols tx + 32*j
    const int ty = tid >> 5;         // row group: rows ty + 8*i (== warp id)
    const int base = blockIdx.x * TM;

    // Stage derived first-layer weights + small vectors.
    for (int idx = tid; idx < 64 * 256; idx += 256)
        sW[idx] = g_Wfd[idx];
    sbias[tid] = g_bias[tid];
    sg[tid]  = ln_g[tid];
    sb[tid]  = ln_b[tid];
    sb2[tid] = proj_b2[tid];

    // Phase 1: tiny MLP hidden activations a1[t][0:32]=f0_h, [32:64]=dur_h
    for (int idx = tid; idx < TM * 64; idx += 256) {
        const int t = idx >> 6;
        const int u = idx & 63;
        int row = base + t; if (row >= npos) row = npos - 1;
        float v;
        if (u < 32) v = f0[row] * f0_w1[u] + f0_b1[u];
        else        v = duration[row] * dur_w1[u - 32] + dur_b1[u - 32];
        sa1[idx] = fmaxf(v, 0.f);
    }
    __syncthreads();

    // Phase 2: GEMM1 (K=64) + bias + phone/midi table rows -> h
    float acc[8][8];
    #pragma unroll
    for (int i = 0; i < 8; i++) {
        int row = base + ty + 8 * i; if (row >= npos) row = npos - 1;
        const int p = phone[row];
        const int m = midi[row];
        const float* __restrict__ pp = &g_phoneP[p * 256];
        const float* __restrict__ mp = &g_midiP[m * 256];
        #pragma unroll
        for (int j = 0; j < 8; j++) {
            const int c = tx + 32 * j;
            acc[i][j] = sbias[c] + pp[c] + mp[c];
        }
    }
    #pragma unroll 4
    for (int k = 0; k < 64; k++) {
        float breg[8], areg[8];
        #pragma unroll
        for (int j = 0; j < 8; j++) breg[j] = sW[k * 256 + tx + 32 * j];
        #pragma unroll
        for (int i = 0; i < 8; i++) areg[i] = sa1[(ty + 8 * i) * 64 + k];
        #pragma unroll
        for (int i = 0; i < 8; i++)
            #pragma unroll
            for (int j = 0; j < 8; j++)
                acc[i][j] += areg[i] * breg[j];
    }
    #pragma unroll
    for (int i = 0; i < 8; i++)
        #pragma unroll
        for (int j = 0; j < 8; j++)
            sA[(ty + 8 * i) * 257 + tx + 32 * j] = acc[i][j];
    __syncthreads();

    // Phase 3: LayerNorm + ReLU. Warp ty handles positions ty*8 .. ty*8+7.
    for (int t8 = 0; t8 < 8; t8++) {
        const int t = ty * 8 + t8;
        float v[8];
        float s = 0.f, ss = 0.f;
        #pragma unroll
        for (int e = 0; e < 8; e++) {
            v[e] = sA[t * 257 + tx + 32 * e];
            s += v[e]; ss += v[e] * v[e];
        }
        #pragma unroll
        for (int o = 16; o > 0; o >>= 1) {
            s  += __shfl_xor_sync(0xffffffffu, s, o);
            ss += __shfl_xor_sync(0xffffffffu, ss, o);
        }
        const float mu  = s * (1.f / 256.f);
        float var = ss * (1.f / 256.f) - mu * mu;
        var = fmaxf(var, 0.f);
        const float rs = rsqrtf(var + EPS);
        #pragma unroll
        for (int e = 0; e < 8; e++) {
            const int c = tx + 32 * e;
            const float hv = (v[e] - mu) * rs * sg[c] + sb[c];
            sA[t * 257 + c] = fmaxf(hv, 0.f);
        }
    }
    __syncthreads();

    // Phase 4: GEMM2 (K=256 in 4 chunks of 64, W2 staged through sW).
    float acc2[8][8];
    #pragma unroll
    for (int i = 0; i < 8; i++)
        #pragma unroll
        for (int j = 0; j < 8; j++)
            acc2[i][j] = sb2[tx + 32 * j];

    for (int chunk = 0; chunk < 4; chunk++) {
        for (int idx = tid; idx < 64 * 256; idx += 256)
            sW[idx] = proj_w2[chunk * 64 * 256 + idx];
        __syncthreads();
        const int kg0 = chunk * 64;
        #pragma unroll 4
        for (int k = 0; k < 64; k++) {
            float breg[8], areg[8];
            #pragma unroll
            for (int j = 0; j < 8; j++) breg[j] = sW[k * 256 + tx + 32 * j];
            #pragma unroll
            for (int i = 0; i < 8; i++) areg[i] = sA[(ty + 8 * i) * 257 + kg0 + k];
            #pragma unroll
            for (int i = 0; i < 8; i++)
                #pragma unroll
                for (int j = 0; j < 8; j++)
                    acc2[i][j] += areg[i] * breg[j];
        }
        __syncthreads();
    }

    // Phase 5: write output.
    #pragma unroll
    for (int i = 0; i < 8; i++) {
        const int row = base + ty + 8 * i;
        if (row < npos) {
            #pragma unroll
            for (int j = 0; j < 8; j++)
                out[row * 256 + tx + 32 * j] = acc2[i][j];
        }
    }
}

extern "C" void kernel_launch(void* const* d_in, const int* in_sizes, int n_in,
                              void* d_out, int out_size) {
    const float* f0          = (const float*)d_in[0];
    const int*   phone       = (const int*)  d_in[1];
    const float* duration    = (const float*)d_in[2];
    const int*   midi        = (const int*)  d_in[3];
    const float* f0_w1       = (const float*)d_in[4];
    const float* f0_b1       = (const float*)d_in[5];
    const float* f0_w2       = (const float*)d_in[6];
    const float* f0_b2       = (const float*)d_in[7];
    const float* phone_table = (const float*)d_in[8];
    const float* midi_table  = (const float*)d_in[9];
    const float* dur_w1      = (const float*)d_in[10];
    const float* dur_b1      = (const float*)d_in[11];
    const float* dur_w2      = (const float*)d_in[12];
    const float* dur_b2      = (const float*)d_in[13];
    const float* proj_w1     = (const float*)d_in[14];
    const float* proj_b1     = (const float*)d_in[15];
    const float* ln_g        = (const float*)d_in[16];
    const float* ln_b        = (const float*)d_in[17];
    const float* proj_w2     = (const float*)d_in[18];
    const float* proj_b2     = (const float*)d_in[19];
    float* out = (float*)d_out;
    const int npos = in_sizes[0];

    precompute_kernel<<<293, 256>>>(f0_w2, f0_b2, phone_table, midi_table,
                                    dur_w2, dur_b2, proj_w1, proj_b1);

    const size_t smem_bytes =
        (size_t)(64 * 257 + 64 * 256 + 64 * 64 + 4 * 256) * sizeof(float);
    cudaFuncSetAttribute(cond_enc_main_kernel,
                         cudaFuncAttributeMaxDynamicSharedMemorySize,
                         (int)smem_bytes);
    const int grid = (npos + TM - 1) / TM;
    cond_enc_main_kernel<<<grid, 256, smem_bytes>>>(
        f0, phone, duration, midi, f0_w1, f0_b1, dur_w1, dur_b1,
        ln_g, ln_b, proj_w2, proj_b2, out, npos);
}

// round 2
// speedup vs baseline: 2.5822x; 2.5822x over previous
#include <cuda_runtime.h>

#define TM 128
#define EPS 1e-5f

// ---------------- device scratch (no allocation allowed) ----------------
__device__ float g_phoneP[100 * 256];  // phone_table @ W1[64:192]   (fp32)
__device__ float g_midiP[128 * 256];   // midi_table  @ W1[192:256]  (fp32)
__device__ float g_WfdT[256 * 64];     // [c][j] transposed derived W1, tf32 bits
__device__ float g_W2T[256 * 256];     // [n][k]  transposed proj_w2, tf32 bits
__device__ float g_bias[256];          // folded bias (fp32)

__device__ __forceinline__ float f2tf32(float f) {
    unsigned u;
    asm("cvt.rna.tf32.f32 %0, %1;" : "=r"(u) : "f"(f));
    return __uint_as_float(u);
}

__device__ __forceinline__ unsigned smem_u32(const void* p) {
    unsigned a;
    asm("{ .reg .u64 t; cvta.to.shared.u64 t, %1; cvt.u32.u64 %0, t; }"
        : "=r"(a) : "l"(p));
    return a;
}

__device__ __forceinline__ void ldsm_x4(unsigned& r0, unsigned& r1,
                                        unsigned& r2, unsigned& r3,
                                        unsigned addr) {
    asm volatile("ldmatrix.sync.aligned.m8n8.x4.shared.b16 {%0,%1,%2,%3}, [%4];"
                 : "=r"(r0), "=r"(r1), "=r"(r2), "=r"(r3) : "r"(addr));
}

__device__ __forceinline__ void mma_tf32(float* c, const unsigned* a,
                                         const unsigned* b) {
    asm volatile(
        "mma.sync.aligned.m16n8k8.row.col.f32.tf32.tf32.f32 "
        "{%0,%1,%2,%3}, {%4,%5,%6,%7}, {%8,%9}, {%0,%1,%2,%3};"
        : "+f"(c[0]), "+f"(c[1]), "+f"(c[2]), "+f"(c[3])
        : "r"(a[0]), "r"(a[1]), "r"(a[2]), "r"(a[3]), "r"(b[0]), "r"(b[1]));
}

// ---------------- precompute ----------------
__global__ void precompute_kernel(
    const float* __restrict__ f0_w2, const float* __restrict__ f0_b2,
    const float* __restrict__ phone_table, const float* __restrict__ midi_table,
    const float* __restrict__ dur_w2, const float* __restrict__ dur_b2,
    const float* __restrict__ proj_w1, const float* __restrict__ proj_b1,
    const float* __restrict__ proj_w2) {
    const int r = blockIdx.x;
    const int c = threadIdx.x;
    if (r < 100) {
        float s = 0.f;
        #pragma unroll 4
        for (int k = 0; k < 128; k++)
            s += phone_table[r * 128 + k] * proj_w1[(64 + k) * 256 + c];
        g_phoneP[r * 256 + c] = s;
    } else if (r < 228) {
        const int m = r - 100;
        float s = 0.f;
        #pragma unroll 4
        for (int k = 0; k < 64; k++)
            s += midi_table[m * 64 + k] * proj_w1[(192 + k) * 256 + c];
        g_midiP[m * 256 + c] = s;
    } else if (r < 260) {
        const int j = r - 228;  // f0 hidden index 0..31
        float s = 0.f;
        #pragma unroll 4
        for (int k = 0; k < 64; k++)
            s += f0_w2[j * 64 + k] * proj_w1[k * 256 + c];
        g_WfdT[c * 64 + j] = f2tf32(s);
    } else if (r < 292) {
        const int j = r - 260;  // dur hidden index -> rows 32..63
        float s = 0.f;
        #pragma unroll 4
        for (int k = 0; k < 64; k++)
            s += dur_w2[j * 64 + k] * proj_w1[(256 + k) * 256 + c];
        g_WfdT[c * 64 + 32 + j] = f2tf32(s);
    } else if (r < 293) {
        float s = proj_b1[c];
        for (int k = 0; k < 64; k++) {
            s += f0_b2[k] * proj_w1[k * 256 + c];
            s += dur_b2[k] * proj_w1[(256 + k) * 256 + c];
        }
        g_bias[c] = s;
    } else {
        const int k = r - 293;  // 0..255: transpose proj_w2 row k
        g_W2T[c * 256 + k] = f2tf32(proj_w2[k * 256 + c]);
    }
}

// ---------------- main fused kernel ----------------
// smem strides chosen so row-to-row offset == 16 B (mod 128 B): conflict-free LDSM.
#define SA1_STRIDE 68   // [128][68]
#define SH_STRIDE 260   // [128][260]
#define SW_STRIDE 36    // [256][36]  (k-chunk of 32)

__global__ __launch_bounds__(256, 1)
void cond_enc_mma_kernel(
    const float* __restrict__ f0, const int* __restrict__ phone,
    const float* __restrict__ duration, const int* __restrict__ midi,
    const float* __restrict__ f0_w1, const float* __restrict__ f0_b1,
    const float* __restrict__ dur_w1, const float* __restrict__ dur_b1,
    const float* __restrict__ ln_g, const float* __restrict__ ln_b,
    const float* __restrict__ proj_b2,
    float* __restrict__ out, int npos) {
    extern __shared__ float sm[];
    float* sH = sm;                       // [128][260] h / activations
    float* sa1 = sH + 128 * SH_STRIDE;    // [128][68] tiny-MLP activations (tf32)
    float* sWT = sa1 + 128 * SA1_STRIDE;  // [256][36] weight k-chunk (tf32, [n][k])
    float* sbias = sWT + 256 * SW_STRIDE; // [256]
    float* sg = sbias + 256;
    float* sb = sg + 256;
    float* sb2 = sb + 256;

    const int tid = threadIdx.x;
    const int lane = tid & 31;
    const int w = tid >> 5;
    const int wy = w & 1;   // row group (64 rows)
    const int wx = w >> 1;  // col group (64 cols)
    const int m0w = wy * 64;
    const int n0w = wx * 64;
    const int gid = lane >> 2;
    const int q = lane & 3;
    const int base = blockIdx.x * TM;

    // ldmatrix per-lane offsets
    const int tA = lane >> 3;
    const int aRow = (lane & 7) + (tA & 1) * 8;
    const int aKof = (tA >> 1) * 4;
    const int bN = (lane & 7) + ((tA >> 1) & 1) * 8;
    const int bKof = (tA & 1) * 4;

    const unsigned u_sa1 = smem_u32(sa1);
    const unsigned u_sH = smem_u32(sH);
    const unsigned u_sWT = smem_u32(sWT);

    // small vectors
    sbias[tid] = g_bias[tid];
    sg[tid] = ln_g[tid];
    sb[tid] = ln_b[tid];
    sb2[tid] = proj_b2[tid];

    // Phase 1: tiny MLPs -> sa1 (tf32)
    for (int idx = tid; idx < TM * 64; idx += 256) {
        const int t = idx >> 6;
        const int u = idx & 63;
        int row = base + t; if (row >= npos) row = npos - 1;
        float v;
        if (u < 32) v = f0[row] * f0_w1[u] + f0_b1[u];
        else        v = duration[row] * dur_w1[u - 32] + dur_b1[u - 32];
        sa1[t * SA1_STRIDE + u] = f2tf32(fmaxf(v, 0.f));
    }

    float acc[4][8][4];
    #pragma unroll
    for (int mt = 0; mt < 4; mt++)
        #pragma unroll
        for (int nt = 0; nt < 8; nt++)
            #pragma unroll
            for (int e = 0; e < 4; e++) acc[mt][nt][e] = 0.f;

    // Phase 2: GEMM1 (K=64 in 2 chunks of 32) on tensor cores
    #pragma unroll
    for (int chunk = 0; chunk < 2; chunk++) {
        __syncthreads();
        #pragma unroll
        for (int rr = 0; rr < 8; rr++) {
            const int n = (tid >> 3) + 32 * rr;
            const int kl4 = tid & 7;
            const float4 v = *(const float4*)&g_WfdT[n * 64 + chunk * 32 + kl4 * 4];
            *(float4*)&sWT[n * SW_STRIDE + kl4 * 4] = v;
        }
        __syncthreads();
        #pragma unroll
        for (int ks = 0; ks < 4; ks++) {
            const int k0 = ks * 8;
            unsigned a[4][4], b[8][2];
            #pragma unroll
            for (int mt = 0; mt < 4; mt++)
                ldsm_x4(a[mt][0], a[mt][1], a[mt][2], a[mt][3],
                        u_sa1 + ((m0w + mt * 16 + aRow) * SA1_STRIDE +
                                 chunk * 32 + k0 + aKof) * 4);
            #pragma unroll
            for (int np = 0; np < 4; np++)
                ldsm_x4(b[2 * np][0], b[2 * np][1], b[2 * np + 1][0], b[2 * np + 1][1],
                        u_sWT + ((n0w + np * 16 + bN) * SW_STRIDE + k0 + bKof) * 4);
            #pragma unroll
            for (int mt = 0; mt < 4; mt++)
                #pragma unroll
                for (int nt = 0; nt < 8; nt++)
                    mma_tf32(acc[mt][nt], a[mt], b[nt]);
        }
    }

    // Epilogue1: acc -> sH
    #pragma unroll
    for (int mt = 0; mt < 4; mt++) {
        const int row = m0w + mt * 16 + gid;
        #pragma unroll
        for (int nt = 0; nt < 8; nt++) {
            const int col = n0w + nt * 8 + q * 2;
            *(float2*)&sH[row * SH_STRIDE + col] =
                make_float2(acc[mt][nt][0], acc[mt][nt][1]);
            *(float2*)&sH[(row + 8) * SH_STRIDE + col] =
                make_float2(acc[mt][nt][2], acc[mt][nt][3]);
        }
    }
    __syncthreads();

    // Phase 3: add bias + phone/midi table rows, LayerNorm, ReLU (warp per row)
    for (int rr = 0; rr < 16; rr++) {
        const int r = w * 16 + rr;
        int grow = base + r; if (grow >= npos) grow = npos - 1;
        const int p = phone[grow];
        const int m = midi[grow];
        const float* __restrict__ pp = &g_phoneP[p * 256];
        const float* __restrict__ mp = &g_midiP[m * 256];
        float v[8];
        float s = 0.f, ss = 0.f;
        #pragma unroll
        for (int e = 0; e < 8; e++) {
            const int c = lane + 32 * e;
            v[e] = sH[r * SH_STRIDE + c] + sbias[c] + pp[c] + mp[c];
            s += v[e]; ss += v[e] * v[e];
        }
        #pragma unroll
        for (int o = 16; o > 0; o >>= 1) {
            s += __shfl_xor_sync(0xffffffffu, s, o);
            ss += __shfl_xor_sync(0xffffffffu, ss, o);
        }
        const float mu = s * (1.f / 256.f);
        float var = ss * (1.f / 256.f) - mu * mu;
        var = fmaxf(var, 0.f);
        const float rs = rsqrtf(var + EPS);
        #pragma unroll
        for (int e = 0; e < 8; e++) {
            const int c = lane + 32 * e;
            const float hv = (v[e] - mu) * rs * sg[c] + sb[c];
            sH[r * SH_STRIDE + c] = f2tf32(fmaxf(hv, 0.f));
        }
    }

    // Phase 4: GEMM2 (K=256 in 8 chunks of 32) on tensor cores
    #pragma unroll
    for (int mt = 0; mt < 4; mt++)
        #pragma unroll
        for (int nt = 0; nt < 8; nt++)
            #pragma unroll
            for (int e = 0; e < 4; e++) acc[mt][nt][e] = 0.f;

    for (int chunk = 0; chunk < 8; chunk++) {
        __syncthreads();
        #pragma unroll
        for (int rr = 0; rr < 8; rr++) {
            const int n = (tid >> 3) + 32 * rr;
            const int kl4 = tid & 7;
            const float4 v = *(const float4*)&g_W2T[n * 256 + chunk * 32 + kl4 * 4];
            *(float4*)&sWT[n * SW_STRIDE + kl4 * 4] = v;
        }
        __syncthreads();
        #pragma unroll
        for (int ks = 0; ks < 4; ks++) {
            const int k0 = ks * 8;
            unsigned a[4][4], b[8][2];
            #pragma unroll
            for (int mt = 0; mt < 4; mt++)
                ldsm_x4(a[mt][0], a[mt][1], a[mt][2], a[mt][3],
                        u_sH + ((m0w + mt * 16 + aRow) * SH_STRIDE +
                                chunk * 32 + k0 + aKof) * 4);
            #pragma unroll
            for (int np = 0; np < 4; np++)
                ldsm_x4(b[2 * np][0], b[2 * np][1], b[2 * np + 1][0], b[2 * np + 1][1],
                        u_sWT + ((n0w + np * 16 + bN) * SW_STRIDE + k0 + bKof) * 4);
            #pragma unroll
            for (int mt = 0; mt < 4; mt++)
                #pragma unroll
                for (int nt = 0; nt < 8; nt++)
                    mma_tf32(acc[mt][nt], a[mt], b[nt]);
        }
    }

    // Phase 5: write output (+proj_b2)
    #pragma unroll
    for (int mt = 0; mt < 4; mt++) {
        const int row = m0w + mt * 16 + gid;
        #pragma unroll
        for (int nt = 0; nt < 8; nt++) {
            const int col = n0w + nt * 8 + q * 2;
            const float b2a = sb2[col];
            const float b2b = sb2[col + 1];
            if (base + row < npos)
                *(float2*)&out[(size_t)(base + row) * 256 + col] =
                    make_float2(acc[mt][nt][0] + b2a, acc[mt][nt][1] + b2b);
            if (base + row + 8 < npos)
                *(float2*)&out[(size_t)(base + row + 8) * 256 + col] =
                    make_float2(acc[mt][nt][2] + b2a, acc[mt][nt][3] + b2b);
        }
    }
}

extern "C" void kernel_launch(void* const* d_in, const int* in_sizes, int n_in,
                              void* d_out, int out_size) {
    const float* f0          = (const float*)d_in[0];
    const int*   phone       = (const int*)  d_in[1];
    const float* duration    = (const float*)d_in[2];
    const int*   midi        = (const int*)  d_in[3];
    const float* f0_w1       = (const float*)d_in[4];
    const float* f0_b1       = (const float*)d_in[5];
    const float* f0_w2       = (const float*)d_in[6];
    const float* f0_b2       = (const float*)d_in[7];
    const float* phone_table = (const float*)d_in[8];
    const float* midi_table  = (const float*)d_in[9];
    const float* dur_w1      = (const float*)d_in[10];
    const float* dur_b1      = (const float*)d_in[11];
    const float* dur_w2      = (const float*)d_in[12];
    const float* dur_b2      = (const float*)d_in[13];
    const float* proj_w1     = (const float*)d_in[14];
    const float* proj_b1     = (const float*)d_in[15];
    const float* ln_g        = (const float*)d_in[16];
    const float* ln_b        = (const float*)d_in[17];
    const float* proj_w2     = (const float*)d_in[18];
    const float* proj_b2     = (const float*)d_in[19];
    float* out = (float*)d_out;
    const int npos = in_sizes[0];

    precompute_kernel<<<549, 256>>>(f0_w2, f0_b2, phone_table, midi_table,
                                    dur_w2, dur_b2, proj_w1, proj_b1, proj_w2);

    const size_t smem_bytes =
        (size_t)(128 * SH_STRIDE + 128 * SA1_STRIDE + 256 * SW_STRIDE + 4 * 256) *
        sizeof(float);
    cudaFuncSetAttribute(cond_enc_mma_kernel,
                         cudaFuncAttributeMaxDynamicSharedMemorySize,
                         (int)smem_bytes);
    const int grid = (npos + TM - 1) / TM;
    cond_enc_mma_kernel<<<grid, 256, smem_bytes>>>(
        f0, phone, duration, midi, f0_w1, f0_b1, dur_w1, dur_b1,
        ln_g, ln_b, proj_b2, out, npos);
}

// round 3
// speedup vs baseline: 2.5889x; 1.0026x over previous
#include <cuda_runtime.h>

#define TM 128
#define EPS 1e-5f

// ---------------- device scratch (no allocation allowed) ----------------
__device__ float g_phoneP[100 * 256];  // phone_table @ W1[64:192]   (fp32)
__device__ float g_midiP[128 * 256];   // midi_table  @ W1[192:256]  (fp32)
__device__ float g_WfdT[256 * 64];     // [c][j] transposed derived W1, tf32 bits
__device__ float g_W2T[256 * 256];     // [n][k]  transposed proj_w2, tf32 bits
__device__ float g_bias[256];          // folded bias (fp32)

__device__ __forceinline__ float f2tf32(float f) {
    unsigned u;
    asm("cvt.rna.tf32.f32 %0, %1;" : "=r"(u) : "f"(f));
    return __uint_as_float(u);
}

__device__ __forceinline__ unsigned smem_u32(const void* p) {
    unsigned a;
    asm("{ .reg .u64 t; cvta.to.shared.u64 t, %1; cvt.u32.u64 %0, t; }"
        : "=r"(a) : "l"(p));
    return a;
}

__device__ __forceinline__ void ldsm_x4(unsigned& r0, unsigned& r1,
                                        unsigned& r2, unsigned& r3,
                                        unsigned addr) {
    asm volatile("ldmatrix.sync.aligned.m8n8.x4.shared.b16 {%0,%1,%2,%3}, [%4];"
                 : "=r"(r0), "=r"(r1), "=r"(r2), "=r"(r3) : "r"(addr));
}

__device__ __forceinline__ void mma_tf32(float* c, const unsigned* a,
                                         const unsigned* b) {
    asm volatile(
        "mma.sync.aligned.m16n8k8.row.col.f32.tf32.tf32.f32 "
        "{%0,%1,%2,%3}, {%4,%5,%6,%7}, {%8,%9}, {%0,%1,%2,%3};"
        : "+f"(c[0]), "+f"(c[1]), "+f"(c[2]), "+f"(c[3])
        : "r"(a[0]), "r"(a[1]), "r"(a[2]), "r"(a[3]), "r"(b[0]), "r"(b[1]));
}

// ---------------- precompute ----------------
__global__ void precompute_kernel(
    const float* __restrict__ f0_w2, const float* __restrict__ f0_b2,
    const float* __restrict__ phone_table, const float* __restrict__ midi_table,
    const float* __restrict__ dur_w2, const float* __restrict__ dur_b2,
    const float* __restrict__ proj_w1, const float* __restrict__ proj_b1,
    const float* __restrict__ proj_w2) {
    const int r = blockIdx.x;
    const int c = threadIdx.x;
    if (r < 100) {
        float s = 0.f;
        #pragma unroll 4
        for (int k = 0; k < 128; k++)
            s += phone_table[r * 128 + k] * proj_w1[(64 + k) * 256 + c];
        g_phoneP[r * 256 + c] = s;
    } else if (r < 228) {
        const int m = r - 100;
        float s = 0.f;
        #pragma unroll 4
        for (int k = 0; k < 64; k++)
            s += midi_table[m * 64 + k] * proj_w1[(192 + k) * 256 + c];
        g_midiP[m * 256 + c] = s;
    } else if (r < 260) {
        const int j = r - 228;  // f0 hidden index 0..31
        float s = 0.f;
        #pragma unroll 4
        for (int k = 0; k < 64; k++)
            s += f0_w2[j * 64 + k] * proj_w1[k * 256 + c];
        g_WfdT[c * 64 + j] = f2tf32(s);
    } else if (r < 292) {
        const int j = r - 260;  // dur hidden index -> rows 32..63
        float s = 0.f;
        #pragma unroll 4
        for (int k = 0; k < 64; k++)
            s += dur_w2[j * 64 + k] * proj_w1[(256 + k) * 256 + c];
        g_WfdT[c * 64 + 32 + j] = f2tf32(s);
    } else if (r < 293) {
        float s = proj_b1[c];
        for (int k = 0; k < 64; k++) {
            s += f0_b2[k] * proj_w1[k * 256 + c];
            s += dur_b2[k] * proj_w1[(256 + k) * 256 + c];
        }
        g_bias[c] = s;
    } else {
        const int k = r - 293;  // 0..255: transpose proj_w2 row k
        g_W2T[c * 256 + k] = f2tf32(proj_w2[k * 256 + c]);
    }
}

// ---------------- main fused kernel ----------------
// smem strides chosen so row-to-row offset == 16 B (mod 128 B): conflict-free LDSM.
#define SA1_STRIDE 68   // [128][68]
#define SH_STRIDE 260   // [128][260]
#define SW_STRIDE 36    // [256][36]  (k-chunk of 32)

__global__ __launch_bounds__(256, 1)
void cond_enc_mma_kernel(
    const float* __restrict__ f0, const int* __restrict__ phone,
    const float* __restrict__ duration, const int* __restrict__ midi,
    const float* __restrict__ f0_w1, const float* __restrict__ f0_b1,
    const float* __restrict__ dur_w1, const float* __restrict__ dur_b1,
    const float* __restrict__ ln_g, const float* __restrict__ ln_b,
    const float* __restrict__ proj_b2,
    float* __restrict__ out, int npos) {
    extern __shared__ float sm[];
    float* sH = sm;                       // [128][260] h / activations
    float* sa1 = sH + 128 * SH_STRIDE;    // [128][68] tiny-MLP activations (tf32)
    float* sWT = sa1 + 128 * SA1_STRIDE;  // [256][36] weight k-chunk (tf32, [n][k])
    float* sbias = sWT + 256 * SW_STRIDE; // [256]
    float* sg = sbias + 256;
    float* sb = sg + 256;
    float* sb2 = sb + 256;

    const int tid = threadIdx.x;
    const int lane = tid & 31;
    const int w = tid >> 5;
    const int wy = w & 1;   // row group (64 rows)
    const int wx = w >> 1;  // col group (64 cols)
    const int m0w = wy * 64;
    const int n0w = wx * 64;
    const int gid = lane >> 2;
    const int q = lane & 3;
    const int base = blockIdx.x * TM;

    // ldmatrix per-lane offsets
    const int tA = lane >> 3;
    const int aRow = (lane & 7) + (tA & 1) * 8;
    const int aKof = (tA >> 1) * 4;
    const int bN = (lane & 7) + ((tA >> 1) & 1) * 8;
    const int bKof = (tA & 1) * 4;

    const unsigned u_sa1 = smem_u32(sa1);
    const unsigned u_sH = smem_u32(sH);
    const unsigned u_sWT = smem_u32(sWT);

    // small vectors
    sbias[tid] = g_bias[tid];
    sg[tid] = ln_g[tid];
    sb[tid] = ln_b[tid];
    sb2[tid] = proj_b2[tid];

    // Phase 1: tiny MLPs -> sa1 (tf32)
    for (int idx = tid; idx < TM * 64; idx += 256) {
        const int t = idx >> 6;
        const int u = idx & 63;
        int row = base + t; if (row >= npos) row = npos - 1;
        float v;
        if (u < 32) v = f0[row] * f0_w1[u] + f0_b1[u];
        else        v = duration[row] * dur_w1[u - 32] + dur_b1[u - 32];
        sa1[t * SA1_STRIDE + u] = f2tf32(fmaxf(v, 0.f));
    }

    float acc[4][8][4];
    #pragma unroll
    for (int mt = 0; mt < 4; mt++)
        #pragma unroll
        for (int nt = 0; nt < 8; nt++)
            #pragma unroll
            for (int e = 0; e < 4; e++) acc[mt][nt][e] = 0.f;

    // Phase 2: GEMM1 (K=64 in 2 chunks of 32) on tensor cores
    #pragma unroll
    for (int chunk = 0; chunk < 2; chunk++) {
        __syncthreads();
        #pragma unroll
        for (int rr = 0; rr < 8; rr++) {
            const int n = (tid >> 3) + 32 * rr;
            const int kl4 = tid & 7;
            const float4 v = *(const float4*)&g_WfdT[n * 64 + chunk * 32 + kl4 * 4];
            *(float4*)&sWT[n * SW_STRIDE + kl4 * 4] = v;
        }
        __syncthreads();
        #pragma unroll
        for (int ks = 0; ks < 4; ks++) {
            const int k0 = ks * 8;
            unsigned a[4][4], b[8][2];
            #pragma unroll
            for (int mt = 0; mt < 4; mt++)
                ldsm_x4(a[mt][0], a[mt][1], a[mt][2], a[mt][3],
                        u_sa1 + ((m0w + mt * 16 + aRow) * SA1_STRIDE +
                                 chunk * 32 + k0 + aKof) * 4);
            #pragma unroll
            for (int np = 0; np < 4; np++)
                ldsm_x4(b[2 * np][0], b[2 * np][1], b[2 * np + 1][0], b[2 * np + 1][1],
                        u_sWT + ((n0w + np * 16 + bN) * SW_STRIDE + k0 + bKof) * 4);
            #pragma unroll
            for (int mt = 0; mt < 4; mt++)
                #pragma unroll
                for (int nt = 0; nt < 8; nt++)
                    mma_tf32(acc[mt][nt], a[mt], b[nt]);
        }
    }

    // Epilogue1: acc -> sH
    #pragma unroll
    for (int mt = 0; mt < 4; mt++) {
        const int row = m0w + mt * 16 + gid;
        #pragma unroll
        for (int nt = 0; nt < 8; nt++) {
            const int col = n0w + nt * 8 + q * 2;
            *(float2*)&sH[row * SH_STRIDE + col] =
                make_float2(acc[mt][nt][0], acc[mt][nt][1]);
            *(float2*)&sH[(row + 8) * SH_STRIDE + col] =
                make_float2(acc[mt][nt][2], acc[mt][nt][3]);
        }
    }
    __syncthreads();

    // Phase 3: add bias + phone/midi table rows, LayerNorm, ReLU (warp per row)
    for (int rr = 0; rr < 16; rr++) {
        const int r = w * 16 + rr;
        int grow = base + r; if (grow >= npos) grow = npos - 1;
        const int p = phone[grow];
        const int m = midi[grow];
        const float* __restrict__ pp = &g_phoneP[p * 256];
        const float* __restrict__ mp = &g_midiP[m * 256];
        float v[8];
        float s = 0.f, ss = 0.f;
        #pragma unroll
        for (int e = 0; e < 8; e++) {
            const int c = lane + 32 * e;
            v[e] = sH[r * SH_STRIDE + c] + sbias[c] + pp[c] + mp[c];
            s += v[e]; ss += v[e] * v[e];
        }
        #pragma unroll
        for (int o = 16; o > 0; o >>= 1) {
            s += __shfl_xor_sync(0xffffffffu, s, o);
            ss += __shfl_xor_sync(0xffffffffu, ss, o);
        }
        const float mu = s * (1.f / 256.f);
        float var = ss * (1.f / 256.f) - mu * mu;
        var = fmaxf(var, 0.f);
        const float rs = rsqrtf(var + EPS);
        #pragma unroll
        for (int e = 0; e < 8; e++) {
            const int c = lane + 32 * e;
            const float hv = (v[e] - mu) * rs * sg[c] + sb[c];
            sH[r * SH_STRIDE + c] = f2tf32(fmaxf(hv, 0.f));
        }
    }

    // Phase 4: GEMM2 (K=256 in 8 chunks of 32) on tensor cores
    #pragma unroll
    for (int mt = 0; mt < 4; mt++)
        #pragma unroll
        for (int nt = 0; nt < 8; nt++)
            #pragma unroll
            for (int e = 0; e < 4; e++) acc[mt][nt][e] = 0.f;

    for (int chunk = 0; chunk < 8; chunk++) {
        __syncthreads();
        #pragma unroll
        for (int rr = 0; rr < 8; rr++) {
            const int n = (tid >> 3) + 32 * rr;
            const int kl4 = tid & 7;
            const float4 v = *(const float4*)&g_W2T[n * 256 + chunk * 32 + kl4 * 4];
            *(float4*)&sWT[n * SW_STRIDE + kl4 * 4] = v;
        }
        __syncthreads();
        #pragma unroll
        for (int ks = 0; ks < 4; ks++) {
            const int k0 = ks * 8;
            unsigned a[4][4], b[8][2];
            #pragma unroll
            for (int mt = 0; mt < 4; mt++)
                ldsm_x4(a[mt][0], a[mt][1], a[mt][2], a[mt][3],
                        u_sH + ((m0w + mt * 16 + aRow) * SH_STRIDE +
                                chunk * 32 + k0 + aKof) * 4);
            #pragma unroll
            for (int np = 0; np < 4; np++)
                ldsm_x4(b[2 * np][0], b[2 * np][1], b[2 * np + 1][0], b[2 * np + 1][1],
                        u_sWT + ((n0w + np * 16 + bN) * SW_STRIDE + k0 + bKof) * 4);
            #pragma unroll
            for (int mt = 0; mt < 4; mt++)
                #pragma unroll
                for (int nt = 0; nt < 8; nt++)
                    mma_tf32(acc[mt][nt], a[mt], b[nt]);
        }
    }

    // Phase 5: write output (+proj_b2)
    #pragma unroll
    for (int mt = 0; mt < 4; mt++) {
        const int row = m0w + mt * 16 + gid;
        #pragma unroll
        for (int nt = 0; nt < 8; nt++) {
            const int col = n0w + nt * 8 + q * 2;
            const float b2a = sb2[col];
            const float b2b = sb2[col + 1];
            if (base + row < npos)
                *(float2*)&out[(size_t)(base + row) * 256 + col] =
                    make_float2(acc[mt][nt][0] + b2a, acc[mt][nt][1] + b2b);
            if (base + row + 8 < npos)
                *(float2*)&out[(size_t)(base + row + 8) * 256 + col] =
                    make_float2(acc[mt][nt][2] + b2a, acc[mt][nt][3] + b2b);
        }
    }
}

extern "C" void kernel_launch(void* const* d_in, const int* in_sizes, int n_in,
                              void* d_out, int out_size) {
    const float* f0          = (const float*)d_in[0];
    const int*   phone       = (const int*)  d_in[1];
    const float* duration    = (const float*)d_in[2];
    const int*   midi        = (const int*)  d_in[3];
    const float* f0_w1       = (const float*)d_in[4];
    const float* f0_b1       = (const float*)d_in[5];
    const float* f0_w2       = (const float*)d_in[6];
    const float* f0_b2       = (const float*)d_in[7];
    const float* phone_table = (const float*)d_in[8];
    const float* midi_table  = (const float*)d_in[9];
    const float* dur_w1      = (const float*)d_in[10];
    const float* dur_b1      = (const float*)d_in[11];
    const float* dur_w2      = (const float*)d_in[12];
    const float* dur_b2      = (const float*)d_in[13];
    const float* proj_w1     = (const float*)d_in[14];
    const float* proj_b1     = (const float*)d_in[15];
    const float* ln_g        = (const float*)d_in[16];
    const float* ln_b        = (const float*)d_in[17];
    const float* proj_w2     = (const float*)d_in[18];
    const float* proj_b2     = (const float*)d_in[19];
    float* out = (float*)d_out;
    const int npos = in_sizes[0];

    precompute_kernel<<<549, 256>>>(f0_w2, f0_b2, phone_table, midi_table,
                                    dur_w2, dur_b2, proj_w1, proj_b1, proj_w2);

    const size_t smem_bytes =
        (size_t)(128 * SH_STRIDE + 128 * SA1_STRIDE + 256 * SW_STRIDE + 4 * 256) *
        sizeof(float);
    cudaFuncSetAttribute(cond_enc_mma_kernel,
                         cudaFuncAttributeMaxDynamicSharedMemorySize,
                         (int)smem_bytes);
    const int grid = (npos + TM - 1) / TM;
    cond_enc_mma_kernel<<<grid, 256, smem_bytes>>>(
        f0, phone, duration, midi, f0_w1, f0_b1, dur_w1, dur_b1,
        ln_g, ln_b, proj_b2, out, npos);
}

// round 4
// speedup vs baseline: 3.2961x; 1.2732x over previous
#include <cuda_runtime.h>

#define TM 64
#define EPS 1e-5f

#define SH_STRIDE 260   // [64][260] h buffer (row step 16B mod 128B)
#define SA1_STRIDE 68   // [64][68] tiny-MLP acts, ALIASED into sH
#define SW_STRIDE 36    // [256][36] weight k-chunk (k=32)

// ---------------- device scratch ----------------
__device__ float g_phoneP[100 * 256];
__device__ float g_midiP[128 * 256];
__device__ float g_WfdT[256 * 64];     // [n][k] derived W1^T, tf32 bits
__device__ float g_W2T[256 * 256];     // [n][k] proj_w2^T, tf32 bits
__device__ float g_bias[256];

__device__ __forceinline__ float f2tf32(float f) {
    unsigned u;
    asm("cvt.rna.tf32.f32 %0, %1;" : "=r"(u) : "f"(f));
    return __uint_as_float(u);
}

__device__ __forceinline__ unsigned smem_u32(const void* p) {
    unsigned a;
    asm("{ .reg .u64 t; cvta.to.shared.u64 t, %1; cvt.u32.u64 %0, t; }"
        : "=r"(a) : "l"(p));
    return a;
}

__device__ __forceinline__ void ldsm_x4(unsigned& r0, unsigned& r1,
                                        unsigned& r2, unsigned& r3,
                                        unsigned addr) {
    asm volatile("ldmatrix.sync.aligned.m8n8.x4.shared.b16 {%0,%1,%2,%3}, [%4];"
                 : "=r"(r0), "=r"(r1), "=r"(r2), "=r"(r3) : "r"(addr));
}

__device__ __forceinline__ void mma_tf32(float* c, const unsigned* a,
                                         const unsigned* b) {
    asm volatile(
        "mma.sync.aligned.m16n8k8.row.col.f32.tf32.tf32.f32 "
        "{%0,%1,%2,%3}, {%4,%5,%6,%7}, {%8,%9}, {%0,%1,%2,%3};"
        : "+f"(c[0]), "+f"(c[1]), "+f"(c[2]), "+f"(c[3])
        : "r"(a[0]), "r"(a[1]), "r"(a[2]), "r"(a[3]), "r"(b[0]), "r"(b[1]));
}

__device__ __forceinline__ void cp_async16(unsigned saddr, const void* gptr) {
    asm volatile("cp.async.cg.shared.global [%0], [%1], 16;"
                 :: "r"(saddr), "l"(gptr));
}
__device__ __forceinline__ void cp_commit() {
    asm volatile("cp.async.commit_group;" ::: "memory");
}
__device__ __forceinline__ void cp_wait0() {
    asm volatile("cp.async.wait_group 0;" ::: "memory");
}

// Stage one 256x32 tf32 k-chunk into sWT via cp.async (8 x 16B per thread).
__device__ __forceinline__ void stage_chunk(unsigned u_sWT,
                                            const float* __restrict__ gsrc,
                                            int row_len, int chunk, int tid) {
    const int kl4 = tid & 7;
    const int nb = tid >> 3;
    #pragma unroll
    for (int rr = 0; rr < 8; rr++) {
        const int n = nb + 32 * rr;
        cp_async16(u_sWT + (unsigned)(n * SW_STRIDE + kl4 * 4) * 4u,
                   gsrc + n * row_len + chunk * 32 + kl4 * 4);
    }
    cp_commit();
}

// ---------------- precompute ----------------
__global__ void precompute_kernel(
    const float* __restrict__ f0_w2, const float* __restrict__ f0_b2,
    const float* __restrict__ phone_table, const float* __restrict__ midi_table,
    const float* __restrict__ dur_w2, const float* __restrict__ dur_b2,
    const float* __restrict__ proj_w1, const float* __restrict__ proj_b1,
    const float* __restrict__ proj_w2) {
    const int r = blockIdx.x;
    const int c = threadIdx.x;
    if (r < 100) {
        float s = 0.f;
        #pragma unroll 4
        for (int k = 0; k < 128; k++)
            s += phone_table[r * 128 + k] * proj_w1[(64 + k) * 256 + c];
        g_phoneP[r * 256 + c] = s;
    } else if (r < 228) {
        const int m = r - 100;
        float s = 0.f;
        #pragma unroll 4
        for (int k = 0; k < 64; k++)
            s += midi_table[m * 64 + k] * proj_w1[(192 + k) * 256 + c];
        g_midiP[m * 256 + c] = s;
    } else if (r < 260) {
        const int j = r - 228;
        float s = 0.f;
        #pragma unroll 4
        for (int k = 0; k < 64; k++)
            s += f0_w2[j * 64 + k] * proj_w1[k * 256 + c];
        g_WfdT[c * 64 + j] = f2tf32(s);
    } else if (r < 292) {
        const int j = r - 260;
        float s = 0.f;
        #pragma unroll 4
        for (int k = 0; k < 64; k++)
            s += dur_w2[j * 64 + k] * proj_w1[(256 + k) * 256 + c];
        g_WfdT[c * 64 + 32 + j] = f2tf32(s);
    } else if (r < 293) {
        float s = proj_b1[c];
        for (int k = 0; k < 64; k++) {
            s += f0_b2[k] * proj_w1[k * 256 + c];
            s += dur_b2[k] * proj_w1[(256 + k) * 256 + c];
        }
        g_bias[c] = s;
    } else {
        const int k = r - 293;
        g_W2T[c * 256 + k] = f2tf32(proj_w2[k * 256 + c]);
    }
}

// ---------------- main fused kernel (2 CTAs/SM) ----------------
__global__ __launch_bounds__(256, 2)
void cond_enc_mma_kernel(
    const float* __restrict__ f0, const int* __restrict__ phone,
    const float* __restrict__ duration, const int* __restrict__ midi,
    const float* __restrict__ f0_w1, const float* __restrict__ f0_b1,
    const float* __restrict__ dur_w1, const float* __restrict__ dur_b1,
    const float* __restrict__ ln_g, const float* __restrict__ ln_b,
    const float* __restrict__ proj_b2,
    float* __restrict__ out, int npos) {
    extern __shared__ float sm[];
    float* sH = sm;                       // [64][260]; sa1 aliased at base
    float* sa1 = sm;                      // [64][68] (lifetime ends before sH writes)
    float* sWT = sH + 64 * SH_STRIDE;     // [256][36]
    float* sbias = sWT + 256 * SW_STRIDE; // [256]
    float* sg = sbias + 256;
    float* sb = sg + 256;
    float* sb2 = sb + 256;

    const int tid = threadIdx.x;
    const int lane = tid & 31;
    const int w = tid >> 5;
    const int wy = w & 1;    // 2 row groups of 32
    const int wx = w >> 1;   // 4 col groups of 64
    const int m0w = wy * 32;
    const int n0w = wx * 64;
    const int gid = lane >> 2;
    const int q = lane & 3;
    const int base = blockIdx.x * TM;

    const int tA = lane >> 3;
    const int aRow = (lane & 7) + (tA & 1) * 8;
    const int aKof = (tA >> 1) * 4;
    const int bN = (lane & 7) + ((tA >> 1) & 1) * 8;
    const int bKof = (tA & 1) * 4;

    const unsigned u_sa1 = smem_u32(sa1);
    const unsigned u_sH = smem_u32(sH);
    const unsigned u_sWT = smem_u32(sWT);

    // Kick off WfdT chunk 0 immediately; it overlaps phase 1.
    stage_chunk(u_sWT, g_WfdT, 64, 0, tid);

    sbias[tid] = g_bias[tid];
    sg[tid] = ln_g[tid];
    sb[tid] = ln_b[tid];
    sb2[tid] = proj_b2[tid];

    // Phase 1: tiny MLPs -> sa1 (tf32)
    for (int idx = tid; idx < TM * 64; idx += 256) {
        const int t = idx >> 6;
        const int u = idx & 63;
        int row = base + t; if (row >= npos) row = npos - 1;
        float v;
        if (u < 32) v = f0[row] * f0_w1[u] + f0_b1[u];
        else        v = duration[row] * dur_w1[u - 32] + dur_b1[u - 32];
        sa1[t * SA1_STRIDE + u] = f2tf32(fmaxf(v, 0.f));
    }

    float acc[2][8][4];
    #pragma unroll
    for (int mt = 0; mt < 2; mt++)
        #pragma unroll
        for (int nt = 0; nt < 8; nt++)
            #pragma unroll
            for (int e = 0; e < 4; e++) acc[mt][nt][e] = 0.f;

    // Phase 2: GEMM1 (K=64, 2 chunks of 32)
    #pragma unroll
    for (int chunk = 0; chunk < 2; chunk++) {
        cp_wait0();
        __syncthreads();
        #pragma unroll
        for (int ks = 0; ks < 4; ks++) {
            const int k0 = ks * 8;
            unsigned a[2][4], b[8][2];
            #pragma unroll
            for (int mt = 0; mt < 2; mt++)
                ldsm_x4(a[mt][0], a[mt][1], a[mt][2], a[mt][3],
                        u_sa1 + (unsigned)((m0w + mt * 16 + aRow) * SA1_STRIDE +
                                           chunk * 32 + k0 + aKof) * 4u);
            #pragma unroll
            for (int np = 0; np < 4; np++)
                ldsm_x4(b[2 * np][0], b[2 * np][1], b[2 * np + 1][0], b[2 * np + 1][1],
                        u_sWT + (unsigned)((n0w + np * 16 + bN) * SW_STRIDE +
                                           k0 + bKof) * 4u);
            #pragma unroll
            for (int mt = 0; mt < 2; mt++)
                #pragma unroll
                for (int nt = 0; nt < 8; nt++)
                    mma_tf32(acc[mt][nt], a[mt], b[nt]);
        }
        __syncthreads();   // everyone done reading sWT (and, on last iter, sa1)
        if (chunk == 0)
            stage_chunk(u_sWT, g_WfdT, 64, 1, tid);
    }

    // sa1 lifetime over. Stage W2 chunk 0 now; it overlaps epilogue + LN.
    stage_chunk(u_sWT, g_W2T, 256, 0, tid);

    // Epilogue1: acc -> sH (overwrites the sa1 alias region; barrier above protects)
    #pragma unroll
    for (int mt = 0; mt < 2; mt++) {
        const int row = m0w + mt * 16 + gid;
        #pragma unroll
        for (int nt = 0; nt < 8; nt++) {
            const int col = n0w + nt * 8 + q * 2;
            *(float2*)&sH[row * SH_STRIDE + col] =
                make_float2(acc[mt][nt][0], acc[mt][nt][1]);
            *(float2*)&sH[(row + 8) * SH_STRIDE + col] =
                make_float2(acc[mt][nt][2], acc[mt][nt][3]);
        }
    }
    __syncthreads();

    // Phase 3: bias + phone/midi tables, LayerNorm, ReLU (warp per row)
    #pragma unroll 2
    for (int rr = 0; rr < 8; rr++) {
        const int r = w * 8 + rr;
        int grow = base + r; if (grow >= npos) grow = npos - 1;
        const int p = phone[grow];
        const int m = midi[grow];
        const float* __restrict__ pp = &g_phoneP[p * 256];
        const float* __restrict__ mp = &g_midiP[m * 256];
        float v[8];
        float s = 0.f, ss = 0.f;
        #pragma unroll
        for (int e = 0; e < 8; e++) {
            const int c = lane + 32 * e;
            v[e] = sH[r * SH_STRIDE + c] + sbias[c] + pp[c] + mp[c];
            s += v[e]; ss += v[e] * v[e];
        }
        #pragma unroll
        for (int o = 16; o > 0; o >>= 1) {
            s += __shfl_xor_sync(0xffffffffu, s, o);
            ss += __shfl_xor_sync(0xffffffffu, ss, o);
        }
        const float mu = s * (1.f / 256.f);
        float var = ss * (1.f / 256.f) - mu * mu;
        var = fmaxf(var, 0.f);
        const float rs = rsqrtf(var + EPS);
        #pragma unroll
        for (int e = 0; e < 8; e++) {
            const int c = lane + 32 * e;
            const float hv = (v[e] - mu) * rs * sg[c] + sb[c];
            sH[r * SH_STRIDE + c] = f2tf32(fmaxf(hv, 0.f));
        }
    }

    #pragma unroll
    for (int mt = 0; mt < 2; mt++)
        #pragma unroll
        for (int nt = 0; nt < 8; nt++)
            #pragma unroll
            for (int e = 0; e < 4; e++) acc[mt][nt][e] = 0.f;

    // Phase 4: GEMM2 (K=256, 8 chunks of 32)
    for (int chunk = 0; chunk < 8; chunk++) {
        cp_wait0();          // this thread's staged chunk landed
        __syncthreads();     // all threads' chunks landed; LN done (chunk 0)
        #pragma unroll
        for (int ks = 0; ks < 4; ks++) {
            const int k0 = ks * 8;
            unsigned a[2][4], b[8][2];
            #pragma unroll
            for (int mt = 0; mt < 2; mt++)
                ldsm_x4(a[mt][0], a[mt][1], a[mt][2], a[mt][3],
                        u_sH + (unsigned)((m0w + mt * 16 + aRow) * SH_STRIDE +
                                          chunk * 32 + k0 + aKof) * 4u);
            #pragma unroll
            for (int np = 0; np < 4; np++)
                ldsm_x4(b[2 * np][0], b[2 * np][1], b[2 * np + 1][0], b[2 * np + 1][1],
                        u_sWT + (unsigned)((n0w + np * 16 + bN) * SW_STRIDE +
                                           k0 + bKof) * 4u);
            #pragma unroll
            for (int mt = 0; mt < 2; mt++)
                #pragma unroll
                for (int nt = 0; nt < 8; nt++)
                    mma_tf32(acc[mt][nt], a[mt], b[nt]);
        }
        __syncthreads();     // all reads of sWT done
        if (chunk < 7)
            stage_chunk(u_sWT, g_W2T, 256, chunk + 1, tid);
    }

    // Phase 5: write output (+proj_b2)
    #pragma unroll
    for (int mt = 0; mt < 2; mt++) {
        const int row = m0w + mt * 16 + gid;
        #pragma unroll
        for (int nt = 0; nt < 8; nt++) {
            const int col = n0w + nt * 8 + q * 2;
            const float b2a = sb2[col];
            const float b2b = sb2[col + 1];
            if (base + row < npos)
                *(float2*)&out[(size_t)(base + row) * 256 + col] =
                    make_float2(acc[mt][nt][0] + b2a, acc[mt][nt][1] + b2b);
            if (base + row + 8 < npos)
                *(float2*)&out[(size_t)(base + row + 8) * 256 + col] =
                    make_float2(acc[mt][nt][2] + b2a, acc[mt][nt][3] + b2b);
        }
    }
}

extern "C" void kernel_launch(void* const* d_in, const int* in_sizes, int n_in,
                              void* d_out, int out_size) {
    const float* f0          = (const float*)d_in[0];
    const int*   phone       = (const int*)  d_in[1];
    const float* duration    = (const float*)d_in[2];
    const int*   midi        = (const int*)  d_in[3];
    const float* f0_w1       = (const float*)d_in[4];
    const float* f0_b1       = (const float*)d_in[5];
    const float* f0_w2       = (const float*)d_in[6];
    const float* f0_b2       = (const float*)d_in[7];
    const float* phone_table = (const float*)d_in[8];
    const float* midi_table  = (const float*)d_in[9];
    const float* dur_w1      = (const float*)d_in[10];
    const float* dur_b1      = (const float*)d_in[11];
    const float* dur_w2      = (const float*)d_in[12];
    const float* dur_b2      = (const float*)d_in[13];
    const float* proj_w1     = (const float*)d_in[14];
    const float* proj_b1     = (const float*)d_in[15];
    const float* ln_g        = (const float*)d_in[16];
    const float* ln_b        = (const float*)d_in[17];
    const float* proj_w2     = (const float*)d_in[18];
    const float* proj_b2     = (const float*)d_in[19];
    float* out = (float*)d_out;
    const int npos = in_sizes[0];

    precompute_kernel<<<549, 256>>>(f0_w2, f0_b2, phone_table, midi_table,
                                    dur_w2, dur_b2, proj_w1, proj_b1, proj_w2);

    const size_t smem_bytes =
        (size_t)(64 * SH_STRIDE + 256 * SW_STRIDE + 4 * 256) * sizeof(float);
    cudaFuncSetAttribute(cond_enc_mma_kernel,
                         cudaFuncAttributeMaxDynamicSharedMemorySize,
                         (int)smem_bytes);
    const int grid = (npos + TM - 1) / TM;
    cond_enc_mma_kernel<<<grid, 256, smem_bytes>>>(
        f0, phone, duration, midi, f0_w1, f0_b1, dur_w1, dur_b1,
        ln_g, ln_b, proj_b2, out, npos);
}

// round 5
// speedup vs baseline: 4.2232x; 1.2813x over previous
#include <cuda_runtime.h>

#define TM 64
#define EPS 1e-5f

#define SH_STRIDE 260   // [64][260]  (row step 1040B == 16B mod 128B: LDSM conflict-free)
#define SA1_STRIDE 68   // [64][68]   (row step 272B  == 16B mod 128B)

// ---------------- device scratch ----------------
__device__ float g_phoneP[100 * 256];
__device__ float g_midiP[128 * 256];
// Fragment-permuted weights: [kt][n][8] where slot j = 2*(k&3) + ((k>>2)&1).
// Lane l of a warp then loads its exact m16n8k8 B-fragment {b0,b1} as one 8B read:
//   float2 at ((kt*256 + n)*8 + 2*(l&3)),  n = nbase + (l>>2).
__device__ float g_WfdP[8 * 256 * 8];    // K=64  -> 8 k-tiles
__device__ float g_W2P[32 * 256 * 8];    // K=256 -> 32 k-tiles
__device__ float g_bias[256];

__device__ __forceinline__ float f2tf32(float f) {
    unsigned u;
    asm("cvt.rna.tf32.f32 %0, %1;" : "=r"(u) : "f"(f));
    return __uint_as_float(u);
}

__device__ __forceinline__ unsigned smem_u32(const void* p) {
    unsigned a;
    asm("{ .reg .u64 t; cvta.to.shared.u64 t, %1; cvt.u32.u64 %0, t; }"
        : "=r"(a) : "l"(p));
    return a;
}

__device__ __forceinline__ void ldsm_x4(unsigned& r0, unsigned& r1,
                                        unsigned& r2, unsigned& r3,
                                        unsigned addr) {
    asm volatile("ldmatrix.sync.aligned.m8n8.x4.shared.b16 {%0,%1,%2,%3}, [%4];"
                 : "=r"(r0), "=r"(r1), "=r"(r2), "=r"(r3) : "r"(addr));
}

__device__ __forceinline__ void mma_tf32(float* c, const unsigned* a,
                                         const unsigned* b) {
    asm volatile(
        "mma.sync.aligned.m16n8k8.row.col.f32.tf32.tf32.f32 "
        "{%0,%1,%2,%3}, {%4,%5,%6,%7}, {%8,%9}, {%0,%1,%2,%3};"
        : "+f"(c[0]), "+f"(c[1]), "+f"(c[2]), "+f"(c[3])
        : "r"(a[0]), "r"(a[1]), "r"(a[2]), "r"(a[3]), "r"(b[0]), "r"(b[1]));
}

// permuted slot for k within its 8-wide tile
__device__ __forceinline__ int perm8(int k) {
    return 2 * (k & 3) + ((k >> 2) & 1);
}

// ---------------- precompute ----------------
__global__ void precompute_kernel(
    const float* __restrict__ f0_w2, const float* __restrict__ f0_b2,
    const float* __restrict__ phone_table, const float* __restrict__ midi_table,
    const float* __restrict__ dur_w2, const float* __restrict__ dur_b2,
    const float* __restrict__ proj_w1, const float* __restrict__ proj_b1,
    const float* __restrict__ proj_w2) {
    const int r = blockIdx.x;
    const int c = threadIdx.x;
    if (r < 100) {
        float s = 0.f;
        #pragma unroll 4
        for (int k = 0; k < 128; k++)
            s += phone_table[r * 128 + k] * proj_w1[(64 + k) * 256 + c];
        g_phoneP[r * 256 + c] = s;
    } else if (r < 228) {
        const int m = r - 100;
        float s = 0.f;
        #pragma unroll 4
        for (int k = 0; k < 64; k++)
            s += midi_table[m * 64 + k] * proj_w1[(192 + k) * 256 + c];
        g_midiP[m * 256 + c] = s;
    } else if (r < 260) {
        const int kd = r - 228;            // f0 hidden idx 0..31 -> W1d rows 0..31
        float s = 0.f;
        #pragma unroll 4
        for (int k = 0; k < 64; k++)
            s += f0_w2[kd * 64 + k] * proj_w1[k * 256 + c];
        g_WfdP[((kd >> 3) * 256 + c) * 8 + perm8(kd)] = f2tf32(s);
    } else if (r < 292) {
        const int j = r - 260;             // dur hidden idx -> W1d rows 32..63
        const int kd = 32 + j;
        float s = 0.f;
        #pragma unroll 4
        for (int k = 0; k < 64; k++)
            s += dur_w2[j * 64 + k] * proj_w1[(256 + k) * 256 + c];
        g_WfdP[((kd >> 3) * 256 + c) * 8 + perm8(kd)] = f2tf32(s);
    } else if (r < 293) {
        float s = proj_b1[c];
        for (int k = 0; k < 64; k++) {
            s += f0_b2[k] * proj_w1[k * 256 + c];
            s += dur_b2[k] * proj_w1[(256 + k) * 256 + c];
        }
        g_bias[c] = s;
    } else {
        const int k = r - 293;             // 0..255: proj_w2 input-row k, col c
        g_W2P[((k >> 3) * 256 + c) * 8 + perm8(k)] = f2tf32(proj_w2[k * 256 + c]);
    }
}

// ---------------- main fused kernel (2 CTAs/SM, 3 barriers) ----------------
__global__ __launch_bounds__(256, 2)
void cond_enc_mma_kernel(
    const float* __restrict__ f0, const int* __restrict__ phone,
    const float* __restrict__ duration, const int* __restrict__ midi,
    const float* __restrict__ f0_w1, const float* __restrict__ f0_b1,
    const float* __restrict__ dur_w1, const float* __restrict__ dur_b1,
    const float* __restrict__ ln_g, const float* __restrict__ ln_b,
    const float* __restrict__ proj_b2,
    float* __restrict__ out, int npos) {
    extern __shared__ float sm[];
    float* sH = sm;                        // [64][260]
    float* sa1 = sH + 64 * SH_STRIDE;      // [64][68]  (no aliasing)
    float* sbias = sa1 + 64 * SA1_STRIDE;  // [256]
    float* sg = sbias + 256;
    float* sb = sg + 256;
    float* sb2 = sb + 256;

    const int tid = threadIdx.x;
    const int lane = tid & 31;
    const int w = tid >> 5;        // warp w owns cols [w*32, w*32+32), all 64 rows
    const int n0w = w * 32;
    const int gid = lane >> 2;
    const int q = lane & 3;
    const int base = blockIdx.x * TM;

    // ldmatrix per-lane offsets (A operand)
    const int tA = lane >> 3;
    const int aRow = (lane & 7) + (tA & 1) * 8;
    const int aKof = (tA >> 1) * 4;

    const unsigned u_sa1 = smem_u32(sa1);
    const unsigned u_sH = smem_u32(sH);

    // B-fragment base pointers (float2 granularity)
    const float2* __restrict__ W1P = (const float2*)g_WfdP;
    const float2* __restrict__ W2P = (const float2*)g_W2P;
    // lane's n per n-tile and k-slot
    int nIdx[4];
    #pragma unroll
    for (int nt = 0; nt < 4; nt++) nIdx[nt] = n0w + nt * 8 + gid;

    sbias[tid] = g_bias[tid];
    sg[tid] = ln_g[tid];
    sb[tid] = ln_b[tid];
    sb2[tid] = proj_b2[tid];

    // Phase 1: tiny MLPs -> sa1 (tf32)
    for (int idx = tid; idx < TM * 64; idx += 256) {
        const int t = idx >> 6;
        const int u = idx & 63;
        int row = base + t; if (row >= npos) row = npos - 1;
        float v;
        if (u < 32) v = f0[row] * f0_w1[u] + f0_b1[u];
        else        v = duration[row] * dur_w1[u - 32] + dur_b1[u - 32];
        sa1[t * SA1_STRIDE + u] = f2tf32(fmaxf(v, 0.f));
    }
    __syncthreads();   // (1) sa1 ready

    float acc[4][4][4];
    #pragma unroll
    for (int mt = 0; mt < 4; mt++)
        #pragma unroll
        for (int nt = 0; nt < 4; nt++)
            #pragma unroll
            for (int e = 0; e < 4; e++) acc[mt][nt][e] = 0.f;

    // Phase 2: GEMM1 (K=64, 8 k-tiles), B direct from L2, 1-deep pipeline
    {
        float2 bq[2][4];
        #pragma unroll
        for (int nt = 0; nt < 4; nt++)
            bq[0][nt] = W2P == nullptr ? make_float2(0.f, 0.f)
                                       : W1P[(0 * 256 + nIdx[nt]) * 4 + q];
        #pragma unroll
        for (int kt = 0; kt < 8; kt++) {
            const int cur = kt & 1, nxt = cur ^ 1;
            if (kt < 7) {
                #pragma unroll
                for (int nt = 0; nt < 4; nt++)
                    bq[nxt][nt] = W1P[((kt + 1) * 256 + nIdx[nt]) * 4 + q];
            }
            unsigned a[4][4];
            #pragma unroll
            for (int mt = 0; mt < 4; mt++)
                ldsm_x4(a[mt][0], a[mt][1], a[mt][2], a[mt][3],
                        u_sa1 + (unsigned)((mt * 16 + aRow) * SA1_STRIDE +
                                           kt * 8 + aKof) * 4u);
            #pragma unroll
            for (int mt = 0; mt < 4; mt++)
                #pragma unroll
                for (int nt = 0; nt < 4; nt++)
                    mma_tf32(acc[mt][nt], a[mt], (const unsigned*)&bq[cur][nt]);
        }
    }

    // Epilogue1: acc -> sH (disjoint from sa1; no barrier needed before writes)
    #pragma unroll
    for (int mt = 0; mt < 4; mt++) {
        const int row = mt * 16 + gid;
        #pragma unroll
        for (int nt = 0; nt < 4; nt++) {
            const int col = n0w + nt * 8 + q * 2;
            *(float2*)&sH[row * SH_STRIDE + col] =
                make_float2(acc[mt][nt][0], acc[mt][nt][1]);
            *(float2*)&sH[(row + 8) * SH_STRIDE + col] =
                make_float2(acc[mt][nt][2], acc[mt][nt][3]);
        }
    }
    __syncthreads();   // (2) sH(h) complete

    // Phase 3: bias + phone/midi tables, LayerNorm, ReLU (warp per row)
    #pragma unroll 2
    for (int rr = 0; rr < 8; rr++) {
        const int r = w * 8 + rr;
        int grow = base + r; if (grow >= npos) grow = npos - 1;
        const int p = phone[grow];
        const int m = midi[grow];
        const float* __restrict__ pp = &g_phoneP[p * 256];
        const float* __restrict__ mp = &g_midiP[m * 256];
        float v[8];
        float s = 0.f, ss = 0.f;
        #pragma unroll
        for (int e = 0; e < 8; e++) {
            const int c = lane + 32 * e;
            v[e] = sH[r * SH_STRIDE + c] + sbias[c] + pp[c] + mp[c];
            s += v[e]; ss += v[e] * v[e];
        }
        #pragma unroll
        for (int o = 16; o > 0; o >>= 1) {
            s += __shfl_xor_sync(0xffffffffu, s, o);
            ss += __shfl_xor_sync(0xffffffffu, ss, o);
        }
        const float mu = s * (1.f / 256.f);
        float var = ss * (1.f / 256.f) - mu * mu;
        var = fmaxf(var, 0.f);
        const float rs = rsqrtf(var + EPS);
        #pragma unroll
        for (int e = 0; e < 8; e++) {
            const int c = lane + 32 * e;
            const float hv = (v[e] - mu) * rs * sg[c] + sb[c];
            sH[r * SH_STRIDE + c] = f2tf32(fmaxf(hv, 0.f));
        }
    }
    __syncthreads();   // (3) activations ready

    #pragma unroll
    for (int mt = 0; mt < 4; mt++)
        #pragma unroll
        for (int nt = 0; nt < 4; nt++)
            #pragma unroll
            for (int e = 0; e < 4; e++) acc[mt][nt][e] = 0.f;

    // Phase 4: GEMM2 (K=256, 32 k-tiles), barrier-free, B from L2
    {
        float2 bq[2][4];
        #pragma unroll
        for (int nt = 0; nt < 4; nt++)
            bq[0][nt] = W2P[(0 * 256 + nIdx[nt]) * 4 + q];
        #pragma unroll 4
        for (int kt = 0; kt < 32; kt++) {
            const int cur = kt & 1, nxt = cur ^ 1;
            if (kt < 31) {
                #pragma unroll
                for (int nt = 0; nt < 4; nt++)
                    bq[nxt][nt] = W2P[((kt + 1) * 256 + nIdx[nt]) * 4 + q];
            }
            unsigned a[4][4];
            #pragma unroll
            for (int mt = 0; mt < 4; mt++)
                ldsm_x4(a[mt][0], a[mt][1], a[mt][2], a[mt][3],
                        u_sH + (unsigned)((mt * 16 + aRow) * SH_STRIDE +
                                          kt * 8 + aKof) * 4u);
            #pragma unroll
            for (int mt = 0; mt < 4; mt++)
                #pragma unroll
                for (int nt = 0; nt < 4; nt++)
                    mma_tf32(acc[mt][nt], a[mt], (const unsigned*)&bq[cur][nt]);
        }
    }

    // Phase 5: write output (+proj_b2)
    #pragma unroll
    for (int mt = 0; mt < 4; mt++) {
        const int row = mt * 16 + gid;
        #pragma unroll
        for (int nt = 0; nt < 4; nt++) {
            const int col = n0w + nt * 8 + q * 2;
            const float b2a = sb2[col];
            const float b2b = sb2[col + 1];
            if (base + row < npos)
                *(float2*)&out[(size_t)(base + row) * 256 + col] =
                    make_float2(acc[mt][nt][0] + b2a, acc[mt][nt][1] + b2b);
            if (base + row + 8 < npos)
                *(float2*)&out[(size_t)(base + row + 8) * 256 + col] =
                    make_float2(acc[mt][nt][2] + b2a, acc[mt][nt][3] + b2b);
        }
    }
}

extern "C" void kernel_launch(void* const* d_in, const int* in_sizes, int n_in,
                              void* d_out, int out_size) {
    const float* f0          = (const float*)d_in[0];
    const int*   phone       = (const int*)  d_in[1];
    const float* duration    = (const float*)d_in[2];
    const int*   midi        = (const int*)  d_in[3];
    const float* f0_w1       = (const float*)d_in[4];
    const float* f0_b1       = (const float*)d_in[5];
    const float* f0_w2       = (const float*)d_in[6];
    const float* f0_b2       = (const float*)d_in[7];
    const float* phone_table = (const float*)d_in[8];
    const float* midi_table  = (const float*)d_in[9];
    const float* dur_w1      = (const float*)d_in[10];
    const float* dur_b1      = (const float*)d_in[11];
    const float* dur_w2      = (const float*)d_in[12];
    const float* dur_b2      = (const float*)d_in[13];
    const float* proj_w1     = (const float*)d_in[14];
    const float* proj_b1     = (const float*)d_in[15];
    const float* ln_g        = (const float*)d_in[16];
    const float* ln_b        = (const float*)d_in[17];
    const float* proj_w2     = (const float*)d_in[18];
    const float* proj_b2     = (const float*)d_in[19];
    float* out = (float*)d_out;
    const int npos = in_sizes[0];

    precompute_kernel<<<549, 256>>>(f0_w2, f0_b2, phone_table, midi_table,
                                    dur_w2, dur_b2, proj_w1, proj_b1, proj_w2);

    const size_t smem_bytes =
        (size_t)(64 * SH_STRIDE + 64 * SA1_STRIDE + 4 * 256) * sizeof(float);
    cudaFuncSetAttribute(cond_enc_mma_kernel,
                         cudaFuncAttributeMaxDynamicSharedMemorySize,
                         (int)smem_bytes);
    const int grid = (npos + TM - 1) / TM;
    cond_enc_mma_kernel<<<grid, 256, smem_bytes>>>(
        f0, phone, duration, midi, f0_w1, f0_b1, dur_w1, dur_b1,
        ln_g, ln_b, proj_b2, out, npos);
}